// round 1
// baseline (speedup 1.0000x reference)
#include <cuda_runtime.h>
#include <cuda_bf16.h>

// GaussianBlur: 17-tap separable depthwise Gaussian (sigma=2), reflect_101
// borders, on 32x3x512x512 fp32. Algebraic simplification:
//   out = blur(x) + 254/255     (scale/offset folded through the linear blur)
//
// Fused single-pass tiled kernel: load 144x48 input tile (with halo) to smem,
// vertical 17-tap pass into 144x32 smem intermediate, horizontal 17-tap pass,
// write 128x32 output tile. One global read + one global write per element.

#define RAD   8
#define KS    17
#define TW    128
#define TH    32
#define SW    (TW + 2 * RAD)   // 144
#define SH    (TH + 2 * RAD)   // 48
#define IMGN  512

// exp(-(i-8)^2 / (2*2^2)) normalized; matches fp32 reference to ~1e-7.
__constant__ float KG[KS] = {
    6.6916e-05f, 4.3635e-04f, 2.2160e-03f, 8.7643e-03f,
    2.6996e-02f, 6.4760e-02f, 1.2098749e-01f, 1.7603574e-01f,
    1.9947464e-01f,
    1.7603574e-01f, 1.2098749e-01f, 6.4760e-02f, 2.6996e-02f,
    8.7643e-03f, 2.2160e-03f, 4.3635e-04f, 6.6916e-05f
};

__device__ __forceinline__ int mirror(int v) {
    // reflect_101: -1 -> 1, IMGN -> IMGN-2 (single reflection; RAD << IMGN)
    v = (v < 0) ? -v : v;
    v = (v >= IMGN) ? (2 * IMGN - 2 - v) : v;
    return v;
}

__global__ __launch_bounds__(256, 4)
void gaussian_blur_fused(const float* __restrict__ in, float* __restrict__ out) {
    __shared__ float s_in[SH][SW];   // 48*144*4 = 27648 B
    __shared__ float s_mid[TH][SW];  // 32*144*4 = 18432 B

    const int x0 = blockIdx.x * TW;
    const int y0 = blockIdx.y * TH;
    const float* img  = in  + (size_t)blockIdx.z * (IMGN * IMGN);
    float*       oimg = out + (size_t)blockIdx.z * (IMGN * IMGN);
    const int tid = threadIdx.x;

    // ---- load input tile with halo (coalesced; mirror at image edges) ----
    #pragma unroll
    for (int i = tid; i < SW * SH; i += 256) {
        const int sx = i % SW;
        const int sy = i / SW;
        const int gx = mirror(x0 + sx - RAD);
        const int gy = mirror(y0 + sy - RAD);
        s_in[sy][sx] = img[gy * IMGN + gx];
    }
    __syncthreads();

    // ---- vertical 17-tap pass ----
    #pragma unroll
    for (int i = tid; i < SW * TH; i += 256) {
        const int sx = i % SW;
        const int my = i / SW;
        float acc = 0.0f;
        #pragma unroll
        for (int j = 0; j < KS; ++j)
            acc += KG[j] * s_in[my + j][sx];
        s_mid[my][sx] = acc;
    }
    __syncthreads();

    // ---- horizontal 17-tap pass + store (with folded affine constant) ----
    const float OFS = 254.0f / 255.0f;
    #pragma unroll
    for (int i = tid; i < TW * TH; i += 256) {
        const int tx = i % TW;
        const int ty = i / TW;
        float acc = 0.0f;
        #pragma unroll
        for (int j = 0; j < KS; ++j)
            acc += KG[j] * s_mid[ty][tx + j];
        oimg[(size_t)(y0 + ty) * IMGN + (x0 + tx)] = acc + OFS;
    }
}

extern "C" void kernel_launch(void* const* d_in, const int* in_sizes, int n_in,
                              void* d_out, int out_size) {
    const float* in = (const float*)d_in[0];
    float* out = (float*)d_out;
    // 32*3 = 96 channel-images of 512x512
    const int n_imgs = in_sizes[0] / (IMGN * IMGN);
    dim3 grid(IMGN / TW, IMGN / TH, n_imgs);  // (4, 16, 96)
    gaussian_blur_fused<<<grid, 256>>>(in, out);
}

// round 2
// speedup vs baseline: 1.4998x; 1.4998x over previous
#include <cuda_runtime.h>
#include <cuda_bf16.h>

// GaussianBlur: 17-tap separable depthwise Gaussian (sigma=2), reflect_101,
// 32x3x512x512 fp32.  out = blur(x) + 254/255  (affine folded through blur).
//
// R1 -> R2: kernel was L1/smem-crossbar bound (88.7% L1, 16.5% DRAM).
//  - register-blocked sliding-window conv: 8 outputs per thread-task from a
//    24-float register window -> 3 smem reads/output instead of 17.
//  - s_in removed: vertical pass reads its 24-row column strip straight from
//    global (coalesced, L2-cached re-reads). Only s_mid stays in smem.
//  - s_mid row stride 145 (odd) -> conflict-free for lane->row mapping.
//  - taps as compile-time immediates -> FFMA-imm (rt 1 vs 2).

#define RAD   8
#define KS    17
#define TW    128
#define TH    32
#define SW    (TW + 2 * RAD)   // 144
#define SWP   145              // padded odd stride (bank-conflict-free)
#define IMGN  512
#define VT    8                // vertical outputs per task
#define HT    8                // horizontal outputs per task
#define NTHR  256

#define VTASKS (SW * (TH / VT))       // 144 * 4 = 576
#define HTASKS ((TW / HT) * TH)       // 16 * 32 = 512

// Compile-time tap values -> fold to FFMA immediates under full unroll.
__device__ __forceinline__ constexpr float kg(int j) {
    constexpr float K[KS] = {
        6.6916291e-05f, 4.3634902e-04f, 2.2159845e-03f, 8.7641502e-03f,
        2.6995483e-02f, 6.4759664e-02f, 1.2098749e-01f, 1.7603573e-01f,
        1.9947065e-01f,
        1.7603573e-01f, 1.2098749e-01f, 6.4759664e-02f, 2.6995483e-02f,
        8.7641502e-03f, 2.2159845e-03f, 4.3634902e-04f, 6.6916291e-05f
    };
    return K[j];
}

__device__ __forceinline__ int mirror(int v) {
    // reflect_101: -1 -> 1, IMGN -> IMGN-2 (single reflection; RAD << IMGN)
    v = (v < 0) ? -v : v;
    v = (v >= IMGN) ? (2 * IMGN - 2 - v) : v;
    return v;
}

__global__ __launch_bounds__(NTHR)
void gaussian_blur_fused(const float* __restrict__ in, float* __restrict__ out) {
    __shared__ float s_mid[TH * SWP];   // 32 * 145 * 4 = 18560 B

    const int x0 = blockIdx.x * TW;
    const int y0 = blockIdx.y * TH;
    const float* __restrict__ img  = in  + (size_t)blockIdx.z * (IMGN * IMGN);
    float*       __restrict__ oimg = out + (size_t)blockIdx.z * (IMGN * IMGN);
    const int tid = threadIdx.x;

    // ---- vertical pass: global -> registers -> s_mid ----
    // task: one x column (of SW) and one strip of VT consecutive y.
    for (int t = tid; t < VTASKS; t += NTHR) {
        const int x  = t % SW;      // 0..143  (lanes -> consecutive x: coalesced LDG)
        const int ys = t / SW;      // 0..3
        const int gx = mirror(x0 + x - RAD);
        const int yy = y0 + ys * VT - RAD;

        float g[VT + KS - 1];       // 24-row register window
        #pragma unroll
        for (int r = 0; r < VT + KS - 1; ++r)
            g[r] = img[(size_t)mirror(yy + r) * IMGN + gx];

        #pragma unroll
        for (int i = 0; i < VT; ++i) {
            float acc = 0.0f;
            #pragma unroll
            for (int j = 0; j < KS; ++j)
                acc = fmaf(g[i + j], kg(j), acc);
            s_mid[(ys * VT + i) * SWP + x] = acc;
        }
    }
    __syncthreads();

    // ---- horizontal pass: s_mid -> registers -> global ----
    // task: one row and one strip of HT consecutive x outputs.
    // Within a warp: same xs, lanes -> rows 0..31; stride 145 -> conflict-free.
    const float OFS = 254.0f / 255.0f;
    #pragma unroll
    for (int t = tid; t < HTASKS; t += NTHR) {
        const int row = t & (TH - 1);   // TH == 32
        const int xs  = t >> 5;
        const int xb  = xs * HT;

        float m[HT + KS - 1];           // 24-float register window
        #pragma unroll
        for (int j = 0; j < HT + KS - 1; ++j)
            m[j] = s_mid[row * SWP + xb + j];

        float o[HT];
        #pragma unroll
        for (int i = 0; i < HT; ++i) {
            float acc = OFS;
            #pragma unroll
            for (int j = 0; j < KS; ++j)
                acc = fmaf(m[i + j], kg(j), acc);
            o[i] = acc;
        }

        float4* dst = (float4*)(oimg + (size_t)(y0 + row) * IMGN + x0 + xb);
        dst[0] = make_float4(o[0], o[1], o[2], o[3]);
        dst[1] = make_float4(o[4], o[5], o[6], o[7]);
    }
}

extern "C" void kernel_launch(void* const* d_in, const int* in_sizes, int n_in,
                              void* d_out, int out_size) {
    const float* in = (const float*)d_in[0];
    float* out = (float*)d_out;
    const int n_imgs = in_sizes[0] / (IMGN * IMGN);   // 96
    dim3 grid(IMGN / TW, IMGN / TH, n_imgs);          // (4, 16, 96)
    gaussian_blur_fused<<<grid, NTHR>>>(in, out);
}

// round 3
// speedup vs baseline: 2.4167x; 1.6114x over previous
#include <cuda_runtime.h>
#include <cuda_bf16.h>

// GaussianBlur: 17-tap separable depthwise Gaussian (sigma=2), reflect_101,
// 32x3x512x512 fp32.  out = blur(x) + 254/255  (affine folded through blur).
//
// R2 -> R3 (was: nothing saturated; shallow MLP, heavy address ALU, scattered STG):
//  - TH=64 tile, vertical task = 32 outputs from a 48-row register window
//    (read amp 3x -> 1.5x, 48 batched independent LDGs for MLP).
//  - interior CTAs: loads via one base pointer + immediate offsets (0 ALU/load);
//    border CTAs: branchless mirror = min(abs(v), 1022-abs(v)).
//  - s_mid stride 148 (16B-aligned rows, phase-conflict-free); horizontal pass
//    reads LDS.128 contiguous per warp and writes coalesced STG.128 per warp.

#define RAD   8
#define KS    17
#define IMGN  512
#define TW    128
#define TH    64
#define SW    (TW + 2 * RAD)        // 144
#define SWP   148                   // padded stride: %4==0, 20 mod 32 -> phase-conflict-free
#define NTHR  320
#define VT    32                    // vertical outputs per task
#define VWIN  (VT + 2 * RAD)        // 48
#define VTASKS (SW * (TH / VT))     // 288  (single pass over 320 threads)
#define HT    4                     // horizontal outputs per task (one float4)
#define HTASKS ((TW / HT) * TH)     // 2048

// Compile-time taps -> FFMA-imm under full unroll.
__device__ __forceinline__ constexpr float kg(int j) {
    constexpr float K[KS] = {
        6.6916291e-05f, 4.3634902e-04f, 2.2159845e-03f, 8.7641502e-03f,
        2.6995483e-02f, 6.4759664e-02f, 1.2098749e-01f, 1.7603573e-01f,
        1.9947065e-01f,
        1.7603573e-01f, 1.2098749e-01f, 6.4759664e-02f, 2.6995483e-02f,
        8.7641502e-03f, 2.2159845e-03f, 4.3634902e-04f, 6.6916291e-05f
    };
    return K[j];
}

__device__ __forceinline__ int mirror(int v) {
    // reflect_101, valid for |overhang| <= RAD: min(abs(v), 1022 - abs(v))
    const int a = ::abs(v);
    return ::min(a, 2 * (IMGN - 1) - a);
}

__global__ __launch_bounds__(NTHR)
void gaussian_blur_fused(const float* __restrict__ in, float* __restrict__ out) {
    __shared__ __align__(16) float s_mid[TH * SWP];   // 64*148*4 = 37888 B

    const int x0 = blockIdx.x * TW;
    const int y0 = blockIdx.y * TH;
    const float* __restrict__ img  = in  + (size_t)blockIdx.z * (IMGN * IMGN);
    float*       __restrict__ oimg = out + (size_t)blockIdx.z * (IMGN * IMGN);
    const int tid = threadIdx.x;

    // block-uniform: no mirroring needed anywhere in this CTA's halo?
    const bool interior = (x0 >= RAD) && (x0 + TW + RAD <= IMGN) &&
                          (y0 >= RAD) && (y0 + TH + RAD <= IMGN);

    // ---- vertical pass: global -> registers -> s_mid ----
    if (tid < VTASKS) {
        int x = tid, ys = 0;
        if (x >= SW) { x -= SW; ys = 1; }
        const int yy = y0 + ys * VT - RAD;

        float g[VWIN];
        if (interior) {
            const float* __restrict__ p = img + (size_t)yy * IMGN + (x0 + x - RAD);
            #pragma unroll
            for (int r = 0; r < VWIN; ++r)
                g[r] = p[r * IMGN];              // immediate offsets, batched LDGs
        } else {
            const int gx = mirror(x0 + x - RAD);
            #pragma unroll
            for (int r = 0; r < VWIN; ++r)
                g[r] = img[(size_t)mirror(yy + r) * IMGN + gx];
        }

        #pragma unroll
        for (int i = 0; i < VT; ++i) {
            float acc = 0.0f;
            #pragma unroll
            for (int j = 0; j < KS; ++j)
                acc = fmaf(g[i + j], kg(j), acc);
            s_mid[(ys * VT + i) * SWP + x] = acc;
        }
    }
    __syncthreads();

    // ---- horizontal pass: s_mid -> registers -> global (coalesced) ----
    // task: 4 consecutive x outputs of one row. Warp lanes -> consecutive
    // x-segments of the same row: contiguous LDS.128 and coalesced STG.128.
    const float OFS = 254.0f / 255.0f;
    for (int t = tid; t < HTASKS; t += NTHR) {
        const int row = t >> 5;          // TW/HT == 32
        const int xs  = t & 31;

        const float4* __restrict__ src =
            (const float4*)(s_mid + row * SWP) + xs;
        const float4 v0 = src[0], v1 = src[1], v2 = src[2], v3 = src[3], v4 = src[4];
        const float m[HT + KS - 1] = {
            v0.x, v0.y, v0.z, v0.w,  v1.x, v1.y, v1.z, v1.w,
            v2.x, v2.y, v2.z, v2.w,  v3.x, v3.y, v3.z, v3.w,
            v4.x, v4.y, v4.z, v4.w
        };

        float o[HT];
        #pragma unroll
        for (int i = 0; i < HT; ++i) {
            float acc = OFS;
            #pragma unroll
            for (int j = 0; j < KS; ++j)
                acc = fmaf(m[i + j], kg(j), acc);
            o[i] = acc;
        }

        *(float4*)(oimg + (size_t)(y0 + row) * IMGN + x0 + xs * HT) =
            make_float4(o[0], o[1], o[2], o[3]);
    }
}

extern "C" void kernel_launch(void* const* d_in, const int* in_sizes, int n_in,
                              void* d_out, int out_size) {
    const float* in = (const float*)d_in[0];
    float* out = (float*)d_out;
    const int n_imgs = in_sizes[0] / (IMGN * IMGN);   // 96
    dim3 grid(IMGN / TW, IMGN / TH, n_imgs);          // (4, 8, 96)
    gaussian_blur_fused<<<grid, NTHR>>>(in, out);
}